// round 3
// baseline (speedup 1.0000x reference)
#include <cuda_runtime.h>
#include <math.h>

#define BATCH 4
#define NTOK 4096
#define DIMC 192
#define HEADS 8
#define DHEAD 64
#define INNER 512
#define FFD 768
#define MF 266
#define DEPTH 6
#define CPG 24
#define MTOT (BATCH*NTOK)

// ---------------- scratch (device globals; no allocation allowed) ----------------
__device__ float g_h [MTOT*DIMC];
__device__ float g_xn[MTOT*DIMC];
__device__ float g_q [MTOT*INNER];
__device__ float g_k [MTOT*INNER];
__device__ float g_v [MTOT*INNER];
__device__ float g_qp[(long)BATCH*HEADS*NTOK*MF];
__device__ float g_kp[(long)BATCH*HEADS*NTOK*MF];
__device__ float g_ctx[BATCH*HEADS*MF*DHEAD];
__device__ float g_ksum[BATCH*HEADS*MF];
__device__ float g_kpart[BATCH*HEADS*16*MF];
__device__ float g_kmaxp[BATCH*HEADS*8];
__device__ float g_ao[MTOT*INNER];
__device__ float g_ff[MTOT*FFD];
__device__ float g_n1[BATCH*DIMC*NTOK];
__device__ float g_n2[BATCH*DIMC*NTOK];
__device__ float g_c7b[BATCH*96*NTOK];
__device__ float g_c5b[BATCH*48*NTOK];

// ---------------- helpers ----------------
__device__ __forceinline__ float geluf(float x){
    return 0.5f*x*(1.0f+erff(x*0.70710678118654752f));
}

__device__ float brsum(float v, float* sm){
    __syncthreads();
    #pragma unroll
    for(int o=16;o>0;o>>=1) v += __shfl_xor_sync(0xffffffffu, v, o);
    if((threadIdx.x&31)==0) sm[threadIdx.x>>5]=v;
    __syncthreads();
    if(threadIdx.x<32){
        int nw=(blockDim.x+31)>>5;
        float r = (threadIdx.x<nw)? sm[threadIdx.x]:0.f;
        #pragma unroll
        for(int o=16;o>0;o>>=1) r += __shfl_xor_sync(0xffffffffu, r, o);
        if(threadIdx.x==0) sm[0]=r;
    }
    __syncthreads();
    return sm[0];
}

__device__ float brmax(float v, float* sm){
    __syncthreads();
    #pragma unroll
    for(int o=16;o>0;o>>=1) v = fmaxf(v, __shfl_xor_sync(0xffffffffu, v, o));
    if((threadIdx.x&31)==0) sm[threadIdx.x>>5]=v;
    __syncthreads();
    if(threadIdx.x<32){
        int nw=(blockDim.x+31)>>5;
        float r = (threadIdx.x<nw)? sm[threadIdx.x]:-3.4e38f;
        #pragma unroll
        for(int o=16;o>0;o>>=1) r = fmaxf(r, __shfl_xor_sync(0xffffffffu, r, o));
        if(threadIdx.x==0) sm[0]=r;
    }
    __syncthreads();
    return sm[0];
}

// ---------------- generic strided batched GEMM: C = alpha*A.B(+bias)(+C)(gelu) ----------------
// element (i,k) of A at A[i*rsA+k*csA]; (j,k) of B at B[j*rsB+k*csB]; C(i,j) at C[i*rsC+j*csC]
// batch z offset = (z/zdiv)*bs1 + (z%zdiv)*bs2 for each matrix.
template<int GELU,int BETA>
__global__ void __launch_bounds__(256) gemm_kernel(
    const float* __restrict__ A, const float* __restrict__ B,
    float* __restrict__ C, const float* __restrict__ bias,
    int M,int N,int K,int zdiv,
    long bsA1,long bsA2,long bsB1,long bsB2,long bsC1,long bsC2,
    int rsA,int csA,int rsB,int csB,int rsC,int csC,float alpha)
{
    __shared__ float As[16][65];
    __shared__ float Bs[16][65];
    int z = blockIdx.z;
    A += (long)(z/zdiv)*bsA1 + (long)(z%zdiv)*bsA2;
    B += (long)(z/zdiv)*bsB1 + (long)(z%zdiv)*bsB2;
    C += (long)(z/zdiv)*bsC1 + (long)(z%zdiv)*bsC2;
    int m0 = blockIdx.y*64, n0 = blockIdx.x*64;
    int tid = threadIdx.y*16+threadIdx.x;
    float acc[4][4]={};
    for(int k0=0;k0<K;k0+=16){
        #pragma unroll
        for(int e=0;e<4;e++){
            int idx = e*256+tid;
            int i = idx>>4, k = idx&15;
            int gk = k0+k;
            int gi = m0+i;
            As[k][i] = (gi<M && gk<K)? A[(long)gi*rsA + (long)gk*csA] : 0.f;
            int gj = n0+i;
            Bs[k][i] = (gj<N && gk<K)? B[(long)gj*rsB + (long)gk*csB] : 0.f;
        }
        __syncthreads();
        #pragma unroll
        for(int k=0;k<16;k++){
            float ra[4],rb[4];
            #pragma unroll
            for(int a=0;a<4;a++) ra[a]=As[k][threadIdx.y*4+a];
            #pragma unroll
            for(int b=0;b<4;b++) rb[b]=Bs[k][threadIdx.x*4+b];
            #pragma unroll
            for(int a=0;a<4;a++)
            #pragma unroll
            for(int b=0;b<4;b++) acc[a][b] = fmaf(ra[a],rb[b],acc[a][b]);
        }
        __syncthreads();
    }
    #pragma unroll
    for(int a=0;a<4;a++){
        int gi = m0+threadIdx.y*4+a;
        if(gi>=M) continue;
        #pragma unroll
        for(int b=0;b<4;b++){
            int gj = n0+threadIdx.x*4+b;
            if(gj>=N) continue;
            float v = alpha*acc[a][b];
            if(bias) v += bias[gj];
            long off = (long)gi*rsC+(long)gj*csC;
            if(BETA) v += C[off];
            if(GELU) v = geluf(v);
            C[off]=v;
        }
    }
}

// ---------------- model-specific kernels ----------------
__global__ void embed_kernel(const float* __restrict__ x, const float* __restrict__ w,
                             const float* __restrict__ bvec, const float* __restrict__ pos){
    int n=blockIdx.x, d=threadIdx.x;
    int p=n&(NTOK-1);
    float acc=bvec[d]+pos[(long)p*DIMC+d];
    acc = fmaf(x[(long)n*3+0], w[d*3+0], acc);
    acc = fmaf(x[(long)n*3+1], w[d*3+1], acc);
    acc = fmaf(x[(long)n*3+2], w[d*3+2], acc);
    g_h[(long)n*DIMC+d]=acc;
}

__global__ void scalenorm_kernel(const float* __restrict__ in, float* __restrict__ out,
                                 const float* __restrict__ gptr){
    __shared__ float red[32];
    int n=blockIdx.x, d=threadIdx.x;
    float v=in[(long)n*DIMC+d];
    float tot=brsum(v*v,red);
    float norm=sqrtf(tot*(1.0f/DIMC));
    out[(long)n*DIMC+d]=v/fmaxf(norm,1e-5f)*gptr[0];
}

// q features: dd already in g_qp (scaled by dn). qp = ratio*(exp(dd - diag - rowmax)+eps)
__global__ void qfeat_kernel(){
    __shared__ float red[32];
    int n=blockIdx.x, bh=blockIdx.y;
    int b=bh>>3, h=bh&7;
    int t=threadIdx.x;
    float qv=0.f;
    if(t<DHEAD) qv=g_q[((long)(b*NTOK+n))*INNER + h*DHEAD + t];
    float diag = 0.0625f*brsum(qv*qv,red);   // 0.5 * dn^2 = 0.5 * 0.125
    float* row = g_qp + ((long)bh*NTOK+n)*MF;
    float mx=-3.4e38f;
    for(int m=t;m<MF;m+=256) mx=fmaxf(mx,row[m]);
    mx=brmax(mx,red);
    const float ratio = rsqrtf((float)MF);
    for(int m=t;m<MF;m+=256) row[m]=ratio*(expf(row[m]-diag-mx)+1e-4f);
}

__global__ void kmax_kernel(){
    __shared__ float red[32];
    int bh=blockIdx.x, chunk=blockIdx.y;
    const float* base=g_kp+(long)bh*NTOK*MF;
    long s0=(long)chunk*512*MF, s1=s0+(long)512*MF;
    float mx=-3.4e38f;
    for(long i=s0+threadIdx.x;i<s1;i+=256) mx=fmaxf(mx,base[i]);
    mx=brmax(mx,red);
    if(threadIdx.x==0) g_kmaxp[bh*8+chunk]=mx;
}

__global__ void kfeat_kernel(){
    __shared__ float red[32];
    int n=blockIdx.x, bh=blockIdx.y;
    int b=bh>>3, h=bh&7;
    int t=threadIdx.x;
    float kv=0.f;
    if(t<DHEAD) kv=g_k[((long)(b*NTOK+n))*INNER + h*DHEAD + t];
    float diag = 0.0625f*brsum(kv*kv,red);
    float mx=-3.4e38f;
    #pragma unroll
    for(int c=0;c<8;c++) mx=fmaxf(mx,g_kmaxp[bh*8+c]);
    float* row=g_kp+((long)bh*NTOK+n)*MF;
    const float ratio = rsqrtf((float)MF);
    for(int m=t;m<MF;m+=256) row[m]=ratio*(expf(row[m]-diag-mx)+1e-4f);
}

__global__ void ksum1_kernel(){
    int bh=blockIdx.x, chunk=blockIdx.y;
    int m=threadIdx.x;
    if(m>=MF) return;
    const float* base=g_kp+(long)bh*NTOK*MF+(long)chunk*256*MF;
    float s=0.f;
    for(int n=0;n<256;n++) s+=base[(long)n*MF+m];
    g_kpart[((long)bh*16+chunk)*MF+m]=s;
}

__global__ void ksum2_kernel(){
    int bh=blockIdx.x, m=threadIdx.x;
    if(m>=MF) return;
    float s=0.f;
    #pragma unroll
    for(int c=0;c<16;c++) s+=g_kpart[((long)bh*16+c)*MF+m];
    g_ksum[bh*MF+m]=s;
}

__global__ void denomdiv_kernel(){
    __shared__ float red[32];
    int n=blockIdx.x, bh=blockIdx.y;
    int b=bh>>3, h=bh&7;
    int t=threadIdx.x;
    const float* row=g_qp+((long)bh*NTOK+n)*MF;
    const float* ks=g_ksum+bh*MF;
    float s=0.f;
    for(int m=t;m<MF;m+=256) s+=row[m]*ks[m];
    s=brsum(s,red);
    float inv=1.0f/s;
    if(t<DHEAD){
        long off=((long)(b*NTOK+n))*INNER + h*DHEAD + t;
        g_ao[off]*=inv;
    }
}

__global__ void groupnorm_kernel(const float* __restrict__ gamma, const float* __restrict__ beta){
    __shared__ float red[32];
    int b=blockIdx.x>>3, g=blockIdx.x&7;
    long base=((long)b*DIMC+g*CPG)*NTOK;
    float s=0.f, ss=0.f;
    for(int i=threadIdx.x;i<CPG*NTOK;i+=blockDim.x){
        float v=g_n1[base+i]; s+=v; ss+=v*v;
    }
    s=brsum(s,red);
    ss=brsum(ss,red);
    const float cnt=(float)(CPG*NTOK);
    float mean=s/cnt;
    float var=ss/cnt-mean*mean;
    float inv=rsqrtf(var+1e-5f);
    for(int i=threadIdx.x;i<CPG*NTOK;i+=blockDim.x){
        int c=g*CPG+i/NTOK;
        float v=(g_n1[base+i]-mean)*inv;
        g_n1[base+i]=v*gamma[c]+beta[c];
    }
}

// circular grouped conv, 16x16 pixel tile per block, smem halo, fused exact GELU
template<int KS,int ICPG,int OCPG>
__global__ void __launch_bounds__(256) circconv_kernel(
    const float* __restrict__ in, const float* __restrict__ w,
    const float* __restrict__ bias, float* __restrict__ out, int inC, int outC)
{
    const int P=KS/2, TW=16+2*P;
    __shared__ float patch[TW*TW];
    __shared__ float wk[KS*KS];
    int tile=blockIdx.x, o=blockIdx.y, b=blockIdx.z;
    int ty0=(tile>>2)*16, tx0=(tile&3)*16;
    int tx=threadIdx.x&15, ty=threadIdx.x>>4;
    int gbase=(o/OCPG)*ICPG;
    float acc=0.f;
    for(int ic=0;ic<ICPG;ic++){
        const float* ip = in + ((long)(b*inC+gbase+ic))*NTOK;
        __syncthreads();
        for(int idx=threadIdx.x; idx<TW*TW; idx+=256){
            int py=idx/TW, px=idx%TW;
            int sy=(ty0+py-P)&63, sx=(tx0+px-P)&63;
            patch[idx]=ip[sy*64+sx];
        }
        if(threadIdx.x<KS*KS) wk[threadIdx.x]=w[((long)o*ICPG+ic)*KS*KS+threadIdx.x];
        __syncthreads();
        #pragma unroll
        for(int ky=0;ky<KS;ky++)
        #pragma unroll
        for(int kx=0;kx<KS;kx++)
            acc = fmaf(wk[ky*KS+kx], patch[(ty+ky)*TW+tx+kx], acc);
    }
    acc+=bias[o];
    out[((long)(b*outC+o))*NTOK + (ty0+ty)*64 + tx0+tx] = geluf(acc);
}

__global__ void conv1_kernel(const float* __restrict__ w, const float* __restrict__ bias,
                             float* __restrict__ out){
    int idx=blockIdx.x*blockDim.x+threadIdx.x;
    if(idx>=MTOT) return;
    int b=idx>>12, p=idx&(NTOK-1);
    const float* base=g_c5b+(long)b*48*NTOK+p;
    #pragma unroll
    for(int c=0;c<3;c++){
        float acc=bias[c];
        #pragma unroll
        for(int ic=0;ic<48;ic++) acc = fmaf(w[c*48+ic], base[(long)ic*NTOK], acc);
        out[(long)idx*3+c]=acc;
    }
}

// ---------------- host side ----------------
static void run_gemm(int gelu,int beta,
    const float* A,const float* B,float* C,const float* bias,
    int M,int N,int K,int batch,int zdiv,
    long bsA1,long bsA2,long bsB1,long bsB2,long bsC1,long bsC2,
    int rsA,int csA,int rsB,int csB,int rsC,int csC,float alpha)
{
    dim3 grid((N+63)/64,(M+63)/64,batch), blk(16,16);
    if(gelu)
        gemm_kernel<1,0><<<grid,blk>>>(A,B,C,bias,M,N,K,zdiv,bsA1,bsA2,bsB1,bsB2,bsC1,bsC2,rsA,csA,rsB,csB,rsC,csC,alpha);
    else if(beta)
        gemm_kernel<0,1><<<grid,blk>>>(A,B,C,bias,M,N,K,zdiv,bsA1,bsA2,bsB1,bsB2,bsC1,bsC2,rsA,csA,rsB,csB,rsC,csC,alpha);
    else
        gemm_kernel<0,0><<<grid,blk>>>(A,B,C,bias,M,N,K,zdiv,bsA1,bsA2,bsB1,bsB2,bsC1,bsC2,rsA,csA,rsB,csB,rsC,csC,alpha);
}

extern "C" void kernel_launch(void* const* d_in, const int* in_sizes, int n_in,
                              void* d_out, int out_size) {
    (void)in_sizes; (void)n_in; (void)out_size;
    const float* x        =(const float*)d_in[0];
    const float* to_in_w  =(const float*)d_in[1];
    const float* to_in_b  =(const float*)d_in[2];
    const float* pos      =(const float*)d_in[3];
    const float* proj     =(const float*)d_in[4];
    const float* sn_attn_g=(const float*)d_in[5];
    const float* wq       =(const float*)d_in[6];
    const float* wk       =(const float*)d_in[7];
    const float* wv       =(const float*)d_in[8];
    const float* wo       =(const float*)d_in[9];
    const float* bo       =(const float*)d_in[10];
    const float* sn_ff_g  =(const float*)d_in[11];
    const float* w1       =(const float*)d_in[12];
    const float* b1       =(const float*)d_in[13];
    const float* w2       =(const float*)d_in[14];
    const float* b2       =(const float*)d_in[15];
    const float* expand_w =(const float*)d_in[16];
    const float* fwd_w    =(const float*)d_in[17];
    const float* dec_w    =(const float*)d_in[18];
    const float* dec_b    =(const float*)d_in[19];
    const float* gn_g     =(const float*)d_in[20];
    const float* gn_b     =(const float*)d_in[21];
    const float* c9w      =(const float*)d_in[22];
    const float* c9b      =(const float*)d_in[23];
    const float* c7w      =(const float*)d_in[24];
    const float* c7b      =(const float*)d_in[25];
    const float* c5w      =(const float*)d_in[26];
    const float* c5b      =(const float*)d_in[27];
    const float* c1w      =(const float*)d_in[28];
    const float* c1b      =(const float*)d_in[29];
    float* out=(float*)d_out;

    void* p;
    cudaGetSymbolAddress(&p,g_h);   float* h  =(float*)p;
    cudaGetSymbolAddress(&p,g_xn);  float* xn =(float*)p;
    cudaGetSymbolAddress(&p,g_q);   float* q  =(float*)p;
    cudaGetSymbolAddress(&p,g_k);   float* k  =(float*)p;
    cudaGetSymbolAddress(&p,g_v);   float* v  =(float*)p;
    cudaGetSymbolAddress(&p,g_qp);  float* qp =(float*)p;
    cudaGetSymbolAddress(&p,g_kp);  float* kp =(float*)p;
    cudaGetSymbolAddress(&p,g_ctx); float* ctx=(float*)p;
    cudaGetSymbolAddress(&p,g_ao);  float* ao =(float*)p;
    cudaGetSymbolAddress(&p,g_ff);  float* ff =(float*)p;
    cudaGetSymbolAddress(&p,g_n1);  float* n1 =(float*)p;
    cudaGetSymbolAddress(&p,g_n2);  float* n2 =(float*)p;
    cudaGetSymbolAddress(&p,g_c7b); float* c7buf=(float*)p;

    const float dn = 0.35355339059327373f;  // 64^-0.25

    embed_kernel<<<MTOT,DIMC>>>(x,to_in_w,to_in_b,pos);

    for(int i=0;i<DEPTH;i++){
        // ---- attention ----
        scalenorm_kernel<<<MTOT,DIMC>>>(h,xn,sn_attn_g+i);
        run_gemm(0,0, xn, wq+(long)i*INNER*DIMC, q, nullptr, MTOT,INNER,DIMC, 1,1,
                 0,0,0,0,0,0, DIMC,1, DIMC,1, INNER,1, 1.f);
        run_gemm(0,0, xn, wk+(long)i*INNER*DIMC, k, nullptr, MTOT,INNER,DIMC, 1,1,
                 0,0,0,0,0,0, DIMC,1, DIMC,1, INNER,1, 1.f);
        run_gemm(0,0, xn, wv+(long)i*INNER*DIMC, v, nullptr, MTOT,INNER,DIMC, 1,1,
                 0,0,0,0,0,0, DIMC,1, DIMC,1, INNER,1, 1.f);
        // dd_q[b,h,n,m] = dn * q . proj^T   (batched over z=b*8+h)
        run_gemm(0,0, q, proj+(long)i*MF*DHEAD, qp, nullptr, NTOK,MF,DHEAD, 32,8,
                 (long)NTOK*INNER, DHEAD,  0,0,  (long)8*NTOK*MF, (long)NTOK*MF,
                 INNER,1, DHEAD,1, MF,1, dn);
        run_gemm(0,0, k, proj+(long)i*MF*DHEAD, kp, nullptr, NTOK,MF,DHEAD, 32,8,
                 (long)NTOK*INNER, DHEAD,  0,0,  (long)8*NTOK*MF, (long)NTOK*MF,
                 INNER,1, DHEAD,1, MF,1, dn);
        qfeat_kernel<<<dim3(NTOK,32),256>>>();
        kmax_kernel<<<dim3(32,8),256>>>();
        kfeat_kernel<<<dim3(NTOK,32),256>>>();
        ksum1_kernel<<<dim3(32,16),288>>>();
        ksum2_kernel<<<32,288>>>();
        // context[m,d] = sum_n kp[n,m] * v[n,d]
        run_gemm(0,0, kp, v, ctx, nullptr, MF,DHEAD,NTOK, 32,8,
                 (long)8*NTOK*MF, (long)NTOK*MF,
                 (long)NTOK*INNER, DHEAD,
                 (long)8*MF*DHEAD, (long)MF*DHEAD,
                 1,MF, 1,INNER, DHEAD,1, 1.f);
        // out[n,d] = qp . ctx, written as [b,n,h*64+d]
        run_gemm(0,0, qp, ctx, ao, nullptr, NTOK,DHEAD,MF, 32,8,
                 (long)8*NTOK*MF, (long)NTOK*MF,
                 (long)8*MF*DHEAD, (long)MF*DHEAD,
                 (long)NTOK*INNER, DHEAD,
                 MF,1, 1,DHEAD, INNER,1, 1.f);
        denomdiv_kernel<<<dim3(NTOK,32),256>>>();
        // h += ao @ wo^T + bo
        run_gemm(0,1, ao, wo+(long)i*DIMC*INNER, h, bo+(long)i*DIMC, MTOT,DIMC,INNER, 1,1,
                 0,0,0,0,0,0, INNER,1, INNER,1, DIMC,1, 1.f);
        // ---- feed-forward ----
        scalenorm_kernel<<<MTOT,DIMC>>>(h,xn,sn_ff_g+i);
        run_gemm(1,0, xn, w1+(long)i*FFD*DIMC, ff, b1+(long)i*FFD, MTOT,FFD,DIMC, 1,1,
                 0,0,0,0,0,0, DIMC,1, DIMC,1, FFD,1, 1.f);
        run_gemm(0,1, ff, w2+(long)i*DIMC*FFD, h, b2+(long)i*DIMC, MTOT,DIMC,FFD, 1,1,
                 0,0,0,0,0,0, FFD,1, FFD,1, DIMC,1, 1.f);
    }

    // ---- decoder ----
    run_gemm(0,0, h,  expand_w, xn, nullptr, MTOT,DIMC,DIMC, 1,1,
             0,0,0,0,0,0, DIMC,1, DIMC,1, DIMC,1, 1.f);
    run_gemm(0,0, xn, fwd_w,    ff, nullptr, MTOT,DIMC,DIMC, 1,1,
             0,0,0,0,0,0, DIMC,1, DIMC,1, DIMC,1, 1.f);
    // dec_lin, writing NCHW directly (batched over b)
    run_gemm(0,0, ff, dec_w, n1, dec_b, NTOK,DIMC,DIMC, 4,4,
             0,(long)NTOK*DIMC, 0,0, 0,(long)DIMC*NTOK,
             DIMC,1, DIMC,1, 1,NTOK, 1.f);
    groupnorm_kernel<<<32,512>>>(gn_g,gn_b);
    circconv_kernel<9,24,24><<<dim3(16,192,4),256>>>(n1,c9w,c9b,n2,192,192);
    circconv_kernel<7,24,12><<<dim3(16, 96,4),256>>>(n2,c7w,c7b,c7buf,192,96);
    {
        void* pc5; cudaGetSymbolAddress(&pc5,g_c5b);
        circconv_kernel<5,12,6><<<dim3(16, 48,4),256>>>(c7buf,c5w,c5b,(float*)pc5,96,48);
    }
    conv1_kernel<<<(MTOT+127)/128,128>>>(c1w,c1b,out);
}